// round 13
// baseline (speedup 1.0000x reference)
#include <cuda_runtime.h>

// Problem constants (fixed by reference)
#define N_TOK 16384
#define DIM   1024
#define NPATH 8
#define CAP   4096
#define G     4                     // rows per fill block
#define PT    16                    // tokens per prologue thread
#define PTHR  1024                  // prologue threads (1 block)
#define NWARP (PTHR / 32)           // 32 warps

// Scratch (allocation-free: __device__ globals)
__device__ float g_gate[N_TOK];
__device__ int   g_count[NPATH];        // clamped to CAP
__device__ int   g_inv[NPATH * CAP];    // token index for (path, slot)

// ---------------------------------------------------------------------------
// Single-block prologue: route + stable slot assignment, zero cross-block sync.
// Thread t owns tokens [t*16, t*16+16) -> global arrival order is
// (warp, lane, k), which the hierarchical scan reproduces exactly.
// ---------------------------------------------------------------------------
__global__ void __launch_bounds__(PTHR, 1)
prologue_kernel(const float* __restrict__ scores) {
    int tid  = threadIdx.x;
    int warp = tid >> 5;
    int lane = tid & 31;
    int i0   = tid * PT;

    __shared__ int s_wtot[NWARP][NPATH];   // per-warp path totals
    __shared__ int s_wexc[NWARP][NPATH];   // exclusive warp offsets

    const float4* s4 = reinterpret_cast<const float4*>(scores);

    int pth[PT];
    int lcnt[NPATH];
#pragma unroll
    for (int q = 0; q < NPATH; q++) lcnt[q] = 0;

    // ---- argmax route (first-max wins = jnp.argmax) + local histogram ----
#pragma unroll
    for (int k = 0; k < PT; k++) {
        int i = i0 + k;
        float4 a = __ldg(&s4[i * 2 + 0]);
        float4 c = __ldg(&s4[i * 2 + 1]);
        float v[8] = {a.x, a.y, a.z, a.w, c.x, c.y, c.z, c.w};
        int best = 0; float bv = v[0];
#pragma unroll
        for (int q = 1; q < 8; q++)
            if (v[q] > bv) { bv = v[q]; best = q; }
        g_gate[i] = bv;
        pth[k] = best;
#pragma unroll
        for (int q = 0; q < NPATH; q++) lcnt[q] += (best == q);  // static idx
    }

    // ---- pack counts: 4 regs x (2 paths x 16 bits); warp total <= 512 ----
    unsigned pk[4], own[4];
#pragma unroll
    for (int j = 0; j < 4; j++) {
        pk[j]  = (unsigned)lcnt[2 * j] | ((unsigned)lcnt[2 * j + 1] << 16);
        own[j] = pk[j];
    }
    // warp inclusive scan (16-bit fields never overflow)
#pragma unroll
    for (int d = 1; d < 32; d <<= 1) {
#pragma unroll
        for (int j = 0; j < 4; j++) {
            unsigned n = __shfl_up_sync(0xffffffffu, pk[j], d);
            if (lane >= d) pk[j] += n;
        }
    }
    // lane 31 holds warp totals
    if (lane == 31) {
#pragma unroll
        for (int j = 0; j < 4; j++) {
            s_wtot[warp][2 * j]     = (int)(pk[j] & 0xffffu);
            s_wtot[warp][2 * j + 1] = (int)(pk[j] >> 16);
        }
    }
    __syncthreads();

    // ---- tiny serial scan over 32 warp totals, one thread per path ----
    if (tid < NPATH) {
        int off = 0;
#pragma unroll
        for (int w = 0; w < NWARP; w++) {
            s_wexc[w][tid] = off;
            off += s_wtot[w][tid];
        }
        g_count[tid] = off < CAP ? off : CAP;
    }
    __syncthreads();

    // ---- per-thread exclusive base per path (all static indexing) ----
    int base[NPATH];
#pragma unroll
    for (int j = 0; j < 4; j++) {
        unsigned exc = pk[j] - own[j];     // exclusive lane prefix
        base[2 * j]     = s_wexc[warp][2 * j]     + (int)(exc & 0xffffu);
        base[2 * j + 1] = s_wexc[warp][2 * j + 1] + (int)(exc >> 16);
    }

    // ---- emit slots: local rank = earlier same-path tokens of this thread ----
#pragma unroll
    for (int k = 0; k < PT; k++) {
        int p = pth[k];
        int rank = 0;
#pragma unroll
        for (int j = 0; j < PT; j++)
            if (j < k) rank += (pth[j] == p);
        int sb = 0;
#pragma unroll
        for (int q = 0; q < NPATH; q++)    // static-index select of base[p]
            sb += (p == q) ? base[q] : 0;
        int slot = sb + rank;
        if (slot < CAP) g_inv[p * CAP + slot] = i0 + k;   // overflow dropped
    }
}

// ---------------------------------------------------------------------------
// Fill: G=4 rows per block (8192 blocks x 256 thr). int4 load of the 4
// consecutive inv entries, 4 independent gather chains, streaming stores.
// Output written exactly once (198 MB total traffic).
// ---------------------------------------------------------------------------
__global__ void __launch_bounds__(256)
fill_kernel(const float* __restrict__ x, float* __restrict__ out) {
    int row0 = blockIdx.x * G;            // G divides CAP: no path crossing
    int p    = row0 >> 12;
    int t    = threadIdx.x;               // float4 index within row

    int cnt = __ldg(&g_count[p]);
    int4 iv = __ldg(reinterpret_cast<const int4*>(&g_inv[row0]));  // in-bounds
    int ivv[G] = {iv.x, iv.y, iv.z, iv.w};

    bool act[G];
    int  tok[G];
#pragma unroll
    for (int j = 0; j < G; j++) {
        act[j] = ((row0 + j) & (CAP - 1)) < cnt;
        tok[j] = act[j] ? ivv[j] : 0;     // clamp: never index x with stale inv
    }

    float gt[G];
#pragma unroll
    for (int j = 0; j < G; j++)
        gt[j] = act[j] ? __ldg(&g_gate[tok[j]]) : 0.0f;

    float4 v[G];
#pragma unroll
    for (int j = 0; j < G; j++) {
        if (act[j]) {
            const float4* x4 =
                reinterpret_cast<const float4*>(x) + (size_t)tok[j] * (DIM / 4);
            float4 w = __ldg(&x4[t]);
            v[j] = make_float4(w.x * gt[j], w.y * gt[j], w.z * gt[j], w.w * gt[j]);
        } else {
            v[j] = make_float4(0.f, 0.f, 0.f, 0.f);
        }
    }

#pragma unroll
    for (int j = 0; j < G; j++) {
        float4* o4 = reinterpret_cast<float4*>(out) +
                     (size_t)(row0 + j) * (DIM / 4) + t;
        __stcs(o4, v[j]);                 // evict-first: keep x hot in L2
    }
}

// ---------------------------------------------------------------------------
// Launch
// ---------------------------------------------------------------------------
extern "C" void kernel_launch(void* const* d_in, const int* in_sizes, int n_in,
                              void* d_out, int out_size) {
    const float* x      = (const float*)d_in[0];   // [16384, 1024]
    const float* scores = (const float*)d_in[1];   // [16384, 8]
    float*       out    = (float*)d_out;           // [8, 4096, 1024]

    prologue_kernel<<<1, PTHR>>>(scores);
    fill_kernel<<<NPATH * CAP / G, 256>>>(x, out);
}

// round 15
// speedup vs baseline: 1.7949x; 1.7949x over previous
#include <cuda_runtime.h>

// Problem constants (fixed by reference)
#define N_TOK 16384
#define DIM   1024
#define NPATH 8
#define CAP   4096
#define TPB   256
#define NBLK  (N_TOK / TPB)   // 64 routing blocks
#define G     4               // rows per fill block

// Scratch (allocation-free: __device__ globals)
__device__ float    g_gate[N_TOK];
__device__ int      g_blockCount[NBLK * NPATH];
__device__ int      g_count[NPATH];          // clamped to CAP
__device__ int      g_inv[NPATH * CAP];      // token index for (path, slot)
__device__ unsigned g_bar;                   // monotonic epoch counter (never reset)

// ---------------------------------------------------------------------------
// Prologue (64 blocks x 256): route + histogram -> light barrier -> smem scan
// -> stable slot assignment. Barrier is replay-safe (epoch = ticket / NBLK)
// and low-traffic (ld.global.cg poll + nanosleep, no atomic hammering).
// ---------------------------------------------------------------------------
__global__ void __launch_bounds__(TPB)
prologue_kernel(const float* __restrict__ scores) {
    int b    = blockIdx.x;
    int tid  = threadIdx.x;
    int warp = tid >> 5;
    int lane = tid & 31;
    int i    = b * TPB + tid;

    __shared__ int s_cnt[NBLK][NPATH];   // all blocks' counts (copied post-barrier)
    __shared__ int s_hist[NPATH];
    __shared__ int s_off[NPATH];
    __shared__ int wcnt[8][NPATH];

    if (tid < NPATH) s_hist[tid] = 0;
    __syncthreads();

    // ---- Phase 1: argmax (first-max wins = jnp.argmax) + block histogram ----
    const float4* s4 = reinterpret_cast<const float4*>(scores);
    float4 a = s4[i * 2 + 0];
    float4 c = s4[i * 2 + 1];
    float v[8] = {a.x, a.y, a.z, a.w, c.x, c.y, c.z, c.w};
    int best = 0; float bv = v[0];
#pragma unroll
    for (int k = 1; k < 8; k++)
        if (v[k] > bv) { bv = v[k]; best = k; }

    g_gate[i] = bv;
    atomicAdd(&s_hist[best], 1);
    __syncthreads();
    if (tid < NPATH)
        g_blockCount[b * NPATH + tid] = s_hist[tid];
    __threadfence();                      // release counts before arrival
    __syncthreads();

    // ---- Arrival barrier: 1 atomic per block, polite poll ----
    if (tid == 0) {
        unsigned ticket = atomicAdd(&g_bar, 1u);
        unsigned target = ((ticket / NBLK) + 1u) * NBLK;
        for (;;) {
            unsigned cur;
            asm volatile("ld.global.cg.u32 %0, [%1];" : "=r"(cur) : "l"(&g_bar));
            if (cur >= target) break;
            __nanosleep(32);
        }
    }
    __syncthreads();
    __threadfence();                      // acquire: all counts visible

    // ---- Phase 2: parallel copy of counts to smem, then smem scan ----
    if (tid < NBLK) {                     // 64 threads, one int4 pair each
        const int4* src = reinterpret_cast<const int4*>(&g_blockCount[tid * NPATH]);
        int4 c0 = src[0];
        int4 c1 = src[1];
        s_cnt[tid][0] = c0.x; s_cnt[tid][1] = c0.y;
        s_cnt[tid][2] = c0.z; s_cnt[tid][3] = c0.w;
        s_cnt[tid][4] = c1.x; s_cnt[tid][5] = c1.y;
        s_cnt[tid][6] = c1.z; s_cnt[tid][7] = c1.w;
    }
    if (tid < 8 * NPATH) reinterpret_cast<int*>(wcnt)[tid] = 0;
    __syncthreads();

    if (tid < NPATH) {                    // smem-only scan: cheap
        int off = 0, total = 0;
#pragma unroll 8
        for (int bb = 0; bb < NBLK; bb++) {
            int cc = s_cnt[bb][tid];
            if (bb < b) off += cc;
            total += cc;
        }
        s_off[tid] = off;
        if (b == 0) g_count[tid] = total < CAP ? total : CAP;
    }
    __syncthreads();

    // ---- Phase 3: stable intra-block rank via match_any + warp-count scan ----
    unsigned m     = __match_any_sync(0xffffffffu, best);
    int      wrank = __popc(m & ((1u << lane) - 1u));
    if (wrank == 0) wcnt[warp][best] = __popc(m);
    __syncthreads();

    int base = s_off[best];
#pragma unroll
    for (int w = 0; w < 8; w++)
        if (w < warp) base += wcnt[w][best];

    int slot = base + wrank;
    if (slot < CAP) g_inv[best * CAP + slot] = i;   // overflow dropped
}

// ---------------------------------------------------------------------------
// Fill (exact R5 version: 29.95us, 32 regs, occ 80%): G=4 rows per block,
// batched index/gate/data loads -> 4 independent chains, streaming stores.
// Output written exactly once (198 MB total traffic).
// ---------------------------------------------------------------------------
__global__ void __launch_bounds__(TPB)
fill_kernel(const float* __restrict__ x, float* __restrict__ out) {
    int row0 = blockIdx.x * G;            // G divides CAP: no path crossing
    int p    = row0 >> 12;
    int t    = threadIdx.x;               // float4 index within row

    int cnt = __ldg(&g_count[p]);

    bool act[G];
    int  tok[G];
#pragma unroll
    for (int j = 0; j < G; j++) {
        int row = row0 + j;
        act[j] = (row & (CAP - 1)) < cnt;
        tok[j] = act[j] ? __ldg(&g_inv[row]) : 0;
    }

    float gt[G];
#pragma unroll
    for (int j = 0; j < G; j++)
        gt[j] = act[j] ? __ldg(&g_gate[tok[j]]) : 0.0f;

    float4 v[G];
#pragma unroll
    for (int j = 0; j < G; j++) {
        if (act[j]) {
            const float4* x4 =
                reinterpret_cast<const float4*>(x) + (size_t)tok[j] * (DIM / 4);
            float4 w = __ldg(&x4[t]);
            v[j] = make_float4(w.x * gt[j], w.y * gt[j], w.z * gt[j], w.w * gt[j]);
        } else {
            v[j] = make_float4(0.f, 0.f, 0.f, 0.f);
        }
    }

#pragma unroll
    for (int j = 0; j < G; j++) {
        float4* o4 = reinterpret_cast<float4*>(out) +
                     (size_t)(row0 + j) * (DIM / 4) + t;
        __stcs(o4, v[j]);                 // evict-first: keep x hot in L2
    }
}

// ---------------------------------------------------------------------------
// Launch
// ---------------------------------------------------------------------------
extern "C" void kernel_launch(void* const* d_in, const int* in_sizes, int n_in,
                              void* d_out, int out_size) {
    const float* x      = (const float*)d_in[0];   // [16384, 1024]
    const float* scores = (const float*)d_in[1];   // [16384, 8]
    float*       out    = (float*)d_out;           // [8, 4096, 1024]

    prologue_kernel<<<NBLK, TPB>>>(scores);
    fill_kernel<<<NPATH * CAP / G, TPB>>>(x, out);
}